// round 7
// baseline (speedup 1.0000x reference)
#include <cuda_runtime.h>
#include <cuda_bf16.h>
#include <math.h>
#include <cstdint>

#define Bb 2
#define Tt 2048
#define Dd 1024
#define Hh 16
#define HDd 64
#define NEe 17
#define GK 1024

// ---------------- scratch globals ----------------
__device__ __nv_bfloat16 g_xhi[Bb*Tt*Dd],  g_xlo[Bb*Tt*Dd];
__device__ __nv_bfloat16 g_wqThi[3*Dd*Dd], g_wqTlo[3*Dd*Dd];
__device__ __nv_bfloat16 g_wpThi[Dd*Dd],   g_wpTlo[Dd*Dd];
__device__ __nv_bfloat16 g_qhi[Bb*Hh*Tt*HDd], g_qlo[Bb*Hh*Tt*HDd];   // [b,h,t,d] *0.125
__device__ __nv_bfloat16 g_khi[Bb*Hh*Tt*HDd], g_klo[Bb*Hh*Tt*HDd];   // [b,h,t,d]
__device__ __nv_bfloat16 g_vhi[Bb*Hh*Tt*HDd], g_vlo[Bb*Hh*Tt*HDd];   // [b,h,d,t] key-permuted
__device__ __nv_bfloat16 g_aohi[Bb*Tt*Dd], g_aolo[Bb*Tt*Dd];
__device__ uint32_t g_pack[(size_t)Bb*Tt*Tt];

// ---------------- helpers ----------------
__device__ __forceinline__ uint32_t smem_u32(const void* p) {
    uint32_t a;
    asm("{ .reg .u64 t; cvta.to.shared.u64 t, %1; cvt.u32.u64 %0, t; }" : "=r"(a) : "l"(p));
    return a;
}
__device__ __forceinline__ void ldsm4(uint32_t* r, uint32_t addr) {
    asm volatile("ldmatrix.sync.aligned.m8n8.x4.shared.b16 {%0,%1,%2,%3}, [%4];"
        : "=r"(r[0]), "=r"(r[1]), "=r"(r[2]), "=r"(r[3]) : "r"(addr));
}
__device__ __forceinline__ void mma16816(float* c, const uint32_t* a, const uint32_t* b) {
    asm volatile("mma.sync.aligned.m16n8k16.row.col.f32.bf16.bf16.f32 "
        "{%0,%1,%2,%3}, {%4,%5,%6,%7}, {%8,%9}, {%0,%1,%2,%3};"
        : "+f"(c[0]), "+f"(c[1]), "+f"(c[2]), "+f"(c[3])
        : "r"(a[0]), "r"(a[1]), "r"(a[2]), "r"(a[3]), "r"(b[0]), "r"(b[1]));
}
__device__ __forceinline__ void pk2(float a, float b, uint32_t& hi, uint32_t& lo) {
    __nv_bfloat16 ha = __float2bfloat16(a), hb = __float2bfloat16(b);
    __nv_bfloat162 hh(ha, hb); hi = *(uint32_t*)&hh;
    __nv_bfloat162 ll(__float2bfloat16(a - __bfloat162float(ha)),
                      __float2bfloat16(b - __bfloat162float(hb)));
    lo = *(uint32_t*)&ll;
}
__device__ __forceinline__ void cpa16(uint32_t s, const void* g) {
    asm volatile("cp.async.cg.shared.global [%0], [%1], 16;" :: "r"(s), "l"(g));
}
#define CPC()  asm volatile("cp.async.commit_group;" ::: "memory")
#define CPW0() asm volatile("cp.async.wait_group 0;" ::: "memory")

// ---------------- prep kernels ----------------
__global__ __launch_bounds__(256) void split_kernel(const float* __restrict__ s,
                                                    __nv_bfloat16* __restrict__ hi,
                                                    __nv_bfloat16* __restrict__ lo) {
    int i = (blockIdx.x * 256 + threadIdx.x) * 4;
    float4 v = *(const float4*)(s + i);
    float f[4] = {v.x, v.y, v.z, v.w};
    __nv_bfloat16 h[4], l[4];
#pragma unroll
    for (int j = 0; j < 4; j++) {
        h[j] = __float2bfloat16(f[j]);
        l[j] = __float2bfloat16(f[j] - __bfloat162float(h[j]));
    }
    *(__nv_bfloat162*)&hi[i]     = __nv_bfloat162(h[0], h[1]);
    *(__nv_bfloat162*)&hi[i + 2] = __nv_bfloat162(h[2], h[3]);
    *(__nv_bfloat162*)&lo[i]     = __nv_bfloat162(l[0], l[1]);
    *(__nv_bfloat162*)&lo[i + 2] = __nv_bfloat162(l[2], l[3]);
}

__global__ __launch_bounds__(256) void transsplit(const float* __restrict__ W,
                                                  __nv_bfloat16* __restrict__ thi,
                                                  __nv_bfloat16* __restrict__ tlo,
                                                  int Kdim, int Ndim) {
    __shared__ float t[32][33];
    int n0 = blockIdx.x * 32, k0 = blockIdx.y * 32;
    int tx = threadIdx.x, ty = threadIdx.y;
#pragma unroll
    for (int j = 0; j < 32; j += 8)
        t[ty + j][tx] = W[(size_t)(k0 + ty + j) * Ndim + n0 + tx];
    __syncthreads();
#pragma unroll
    for (int j = 0; j < 32; j += 8) {
        float v = t[tx][ty + j];
        __nv_bfloat16 h = __float2bfloat16(v);
        size_t o = (size_t)(n0 + ty + j) * Kdim + k0 + tx;
        thi[o] = h;
        tlo[o] = __float2bfloat16(v - __bfloat162float(h));
    }
}

__global__ __launch_bounds__(256) void pack_bias(const float* __restrict__ adj,
                                                 const int* __restrict__ ety,
                                                 uint32_t* __restrict__ out) {
    size_t i = ((size_t)blockIdx.x * 256 + threadIdx.x) * 4;
    float4 a = *(const float4*)(adj + i);
    int4 t = *(const int4*)(ety + i);
    uint4 r;
    r.x = ((uint32_t)t.x << 16) | (uint32_t)__bfloat16_as_ushort(__float2bfloat16(a.x));
    r.y = ((uint32_t)t.y << 16) | (uint32_t)__bfloat16_as_ushort(__float2bfloat16(a.y));
    r.z = ((uint32_t)t.z << 16) | (uint32_t)__bfloat16_as_ushort(__float2bfloat16(a.z));
    r.w = ((uint32_t)t.w << 16) | (uint32_t)__bfloat16_as_ushort(__float2bfloat16(a.w));
    *(uint4*)(out + i) = r;
}

// ---------------------------------------------------------------------------
// HMMA GEMM, 128x64 tile (warp tile 32x32), cp.async double-buffer, 2 CTAs/SM.
// mode 0: fp32 Cout. mode 1: QKV epilogue -> bf16 hi/lo, Q *0.125,
//   V -> [b,h,d,t] with key-permutation baked in.
// ---------------------------------------------------------------------------
#define KC 32
#define LDP 40
#define TA_B (128 * LDP * 2)             // 10240
#define TB_B (64 * LDP * 2)              // 5760
#define STG_B (2 * TA_B + 2 * TB_B)      // 32000

__global__ __launch_bounds__(256, 2)
void mma_gemm(const __nv_bfloat16* __restrict__ Ahi, const __nv_bfloat16* __restrict__ Alo,
              const __nv_bfloat16* __restrict__ Bhi, const __nv_bfloat16* __restrict__ Blo,
              int Ncols, float* __restrict__ Cout, int mode) {
    extern __shared__ char smem[];
    uint32_t sb = smem_u32(smem);
    int tid = threadIdx.x, wid = tid >> 5, lane = tid & 31;
    int wm = wid & 3, wn = wid >> 2;                 // warp tile rows wm*32, cols wn*32
    int m0 = blockIdx.y * 128, n0 = blockIdx.x * 64;

    // loaders
    int ra = tid >> 1, ca = (tid & 1) * 16;          // A: 2x cpa16 per matrix
    int rb = tid >> 2, cb = (tid & 3) * 8;           // B: 1x cpa16 per matrix
    const __nv_bfloat16* pAh = Ahi + (size_t)m0 * GK + (size_t)ra * GK + ca;
    const __nv_bfloat16* pAl = Alo + (size_t)m0 * GK + (size_t)ra * GK + ca;
    const __nv_bfloat16* pBh = Bhi + (size_t)n0 * GK + (size_t)rb * GK + cb;
    const __nv_bfloat16* pBl = Blo + (size_t)n0 * GK + (size_t)rb * GK + cb;
    uint32_t dA = (uint32_t)(ra * LDP + ca) * 2;
    uint32_t dB = (uint32_t)(rb * LDP + cb) * 2;

#define GLOAD(bs, kof) do {                                                   \
    cpa16((bs) + dA,               pAh + (kof));                              \
    cpa16((bs) + dA + 16,          pAh + (kof) + 8);                          \
    cpa16((bs) + TA_B + dA,        pAl + (kof));                              \
    cpa16((bs) + TA_B + dA + 16,   pAl + (kof) + 8);                          \
    cpa16((bs) + 2 * TA_B + dB,        pBh + (kof));                          \
    cpa16((bs) + 2 * TA_B + TB_B + dB, pBl + (kof));                          \
    CPC();                                                                    \
} while (0)

    uint32_t a_off = (uint32_t)((wm * 32 + (lane & 15)) * LDP + (lane >> 4) * 8) * 2;
    uint32_t b_off = (uint32_t)((wn * 32 + (lane & 7) + (lane >> 4) * 8) * LDP
                                + ((lane >> 3) & 1) * 8) * 2;

    float acc[2][4][4];
#pragma unroll
    for (int i = 0; i < 2; i++)
#pragma unroll
        for (int j = 0; j < 4; j++)
#pragma unroll
            for (int k = 0; k < 4; k++) acc[i][j][k] = 0.f;

    GLOAD(sb, 0);

    const int NCH = GK / KC;
    for (int kc = 0; kc < NCH; kc++) {
        int buf = kc & 1;
        CPW0();
        __syncthreads();
        if (kc + 1 < NCH) GLOAD(sb + (buf ^ 1) * STG_B, (size_t)(kc + 1) * KC);

        uint32_t sAh = sb + buf * STG_B + a_off;
        uint32_t sAl = sAh + TA_B;
        uint32_t sBh = sb + buf * STG_B + 2 * TA_B + b_off;
        uint32_t sBl = sBh + TB_B;
#pragma unroll
        for (int ks = 0; ks < 2; ks++) {
            uint32_t kb = (uint32_t)(ks * 16) * 2;
            uint32_t ah[2][4], al[2][4];
#pragma unroll
            for (int tm = 0; tm < 2; tm++) {
                uint32_t ro = (uint32_t)(tm * 16 * LDP) * 2;
                ldsm4(ah[tm], sAh + ro + kb);
                ldsm4(al[tm], sAl + ro + kb);
            }
#pragma unroll
            for (int pr = 0; pr < 2; pr++) {
                uint32_t po = (uint32_t)(pr * 16 * LDP) * 2;
                uint32_t bh[4], bl[4];
                ldsm4(bh, sBh + po + kb);
                ldsm4(bl, sBl + po + kb);
#pragma unroll
                for (int hf = 0; hf < 2; hf++) {
                    int tn = pr * 2 + hf;
#pragma unroll
                    for (int tm = 0; tm < 2; tm++) {
                        mma16816(acc[tm][tn], ah[tm], bh + hf * 2);
                        mma16816(acc[tm][tn], ah[tm], bl + hf * 2);
                        mma16816(acc[tm][tn], al[tm], bh + hf * 2);
                    }
                }
            }
        }
    }

    int rbase = m0 + wm * 32 + (lane >> 2);
    int cbase = n0 + wn * 32 + (lane & 3) * 2;

    if (mode == 0) {
#pragma unroll
        for (int tm = 0; tm < 2; tm++)
#pragma unroll
            for (int tn = 0; tn < 4; tn++)
#pragma unroll
                for (int half = 0; half < 2; half++) {
                    int m = rbase + tm * 16 + half * 8;
                    *(float2*)&Cout[(size_t)m * Ncols + cbase + tn * 8] =
                        make_float2(acc[tm][tn][half * 2], acc[tm][tn][half * 2 + 1]);
                }
        return;
    }

    int which = n0 >> 10;
    if (which < 2) {
        float sc = (which == 0) ? 0.125f : 1.0f;
        __nv_bfloat16* dh = which ? g_khi : g_qhi;
        __nv_bfloat16* dl = which ? g_klo : g_qlo;
#pragma unroll
        for (int tm = 0; tm < 2; tm++)
#pragma unroll
            for (int tn = 0; tn < 4; tn++)
#pragma unroll
                for (int half = 0; half < 2; half++) {
                    int m = rbase + tm * 16 + half * 8;
                    int n = cbase + tn * 8;
                    int h = (n & 1023) >> 6, d = n & 63;
                    int bI = m >> 11, t = m & 2047;
                    size_t ix = ((size_t)(bI * Hh + h) * Tt + t) * HDd + d;
                    uint32_t uh, ul;
                    pk2(acc[tm][tn][half * 2] * sc, acc[tm][tn][half * 2 + 1] * sc, uh, ul);
                    *(uint32_t*)&dh[ix] = uh;
                    *(uint32_t*)&dl[ix] = ul;
                }
    } else {
        // V: transpose [64 n][128 m] via smem, store [b,h,d,t] key-permuted
        float* buf = (float*)smem;
        __syncthreads();
#pragma unroll
        for (int tm = 0; tm < 2; tm++)
#pragma unroll
            for (int tn = 0; tn < 4; tn++)
#pragma unroll
                for (int half = 0; half < 2; half++) {
                    int nl = wn * 32 + tn * 8 + (lane & 3) * 2;
                    int ml = wm * 32 + (lane >> 2) + tm * 16 + half * 8;
                    buf[nl * 132 + ml]       = acc[tm][tn][half * 2];
                    buf[(nl + 1) * 132 + ml] = acc[tm][tn][half * 2 + 1];
                }
        __syncthreads();
        int nl = tid >> 2, mq = (tid & 3) * 32;      // each thread: 32 t-values
        int n = n0 + nl;
        int h = (n & 1023) >> 6, d = n & 63;
        int bI = m0 >> 11, t0 = m0 & 2047;
        int gb = mq & 64;                            // 64-aligned group base
        int co0 = mq & 32;                           // offset within group
        size_t base = ((size_t)(bI * Hh + h) * HDd + d) * Tt + t0 + gb;
#pragma unroll
        for (int g = 0; g < 4; g++) {
            __nv_bfloat16 hi8[8], lo8[8];
#pragma unroll
            for (int e = 0; e < 8; e++) {
                int c = co0 + g * 8 + e;             // dest index within 64-group
                int src = 16 * ((c >> 1) & 3) + 2 * (c >> 3) + (c & 1);
                float f = buf[nl * 132 + gb + src];
                hi8[e] = __float2bfloat16(f);
                lo8[e] = __float2bfloat16(f - __bfloat162float(hi8[e]));
            }
            *(uint4*)&g_vhi[base + co0 + g * 8] = *(uint4*)hi8;
            *(uint4*)&g_vlo[base + co0 + g * 8] = *(uint4*)lo8;
        }
    }
}

// ---------------------------------------------------------------------------
// HMMA flash attention: q-tile 128, k-tile 64, cp.async double-buffered KV.
// LPT: longest q-tiles launch first.
// ---------------------------------------------------------------------------
#define LQ 72
#define QB (128 * LQ * 2)
#define TB (64 * LQ * 2)
#define OKV (2 * QB)

__global__ __launch_bounds__(256, 2) void attn_mma(
    const uint32_t* __restrict__ pk, const float* __restrict__ adj_bias,
    const float* __restrict__ edge_table) {
    extern __shared__ char sm[];
    uint32_t sB = smem_u32(sm);
    float* ets = (float*)(sm + OKV + 8 * TB);

    int tid = threadIdx.x, w = tid >> 5, lane = tid & 31;
    int qt = (int)(gridDim.x - 1 - blockIdx.x);      // LPT: big tiles first
    int h = blockIdx.y, b = blockIdx.z;
    int q0 = qt * 128, qw = q0 + 16 * w;
    float bco = adj_bias[h];
    if (tid < NEe) ets[tid] = edge_table[tid * Hh + h];

    {   // Q tile (pre-scaled bf16 hi/lo)
        const __nv_bfloat16* qh = g_qhi + ((size_t)(b * Hh + h) * Tt + q0) * HDd;
        const __nv_bfloat16* ql = g_qlo + ((size_t)(b * Hh + h) * Tt + q0) * HDd;
        __nv_bfloat16* sQh = (__nv_bfloat16*)sm;
        __nv_bfloat16* sQl = sQh + 128 * LQ;
        int r = tid >> 1, cg = (tid & 1) * 32;
#pragma unroll
        for (int u = 0; u < 4; u++) {
            *(uint4*)&sQh[r * LQ + cg + u * 8] = *(const uint4*)&qh[(size_t)r * 64 + cg + u * 8];
            *(uint4*)&sQl[r * LQ + cg + u * 8] = *(const uint4*)&ql[(size_t)r * 64 + cg + u * 8];
        }
    }

    int c = tid >> 2, dg = (tid & 3) * 16;
    int gkp = 16 * ((c >> 1) & 3) + 2 * (c >> 3) + (c & 1);
    uint32_t krow = (uint32_t)(c * LQ + dg) * 2;
    const __nv_bfloat16* bkh = g_khi + ((size_t)(b * Hh + h) * Tt + gkp) * HDd + dg;
    const __nv_bfloat16* bkl = g_klo + ((size_t)(b * Hh + h) * Tt + gkp) * HDd + dg;
    const __nv_bfloat16* bvh = g_vhi + ((size_t)(b * Hh + h) * HDd + c) * Tt + dg;
    const __nv_bfloat16* bvl = g_vlo + ((size_t)(b * Hh + h) * HDd + c) * Tt + dg;

#define LOADKV(jt, bf) do {                                                     \
    int _k0 = (jt) * 64;                                                        \
    uint32_t _bs = sB + OKV + (bf) * 4 * TB;                                    \
    cpa16(_bs + krow,               bkh + (size_t)_k0 * HDd);                   \
    cpa16(_bs + krow + 16,          bkh + (size_t)_k0 * HDd + 8);               \
    cpa16(_bs + TB + krow,          bkl + (size_t)_k0 * HDd);                   \
    cpa16(_bs + TB + krow + 16,     bkl + (size_t)_k0 * HDd + 8);               \
    cpa16(_bs + 2 * TB + krow,      bvh + _k0);                                 \
    cpa16(_bs + 2 * TB + krow + 16, bvh + _k0 + 8);                             \
    cpa16(_bs + 3 * TB + krow,      bvl + _k0);                                 \
    cpa16(_bs + 3 * TB + krow + 16, bvl + _k0 + 8);                             \
    CPC();                                                                      \
} while (0)

    float o[8][4];
#pragma unroll
    for (int i = 0; i < 8; i++)
#pragma unroll
        for (int j = 0; j < 4; j++) o[i][j] = 0.f;
    float m0r = -1e30f, m1r = -1e30f, l0r = 0.f, l1r = 0.f;

    LOADKV(0, 0);

    int nkt = 2 * qt + 2;
    for (int jt = 0; jt < nkt; jt++) {
        int k0 = jt * 64;
        int buf = jt & 1;
        CPW0();
        __syncthreads();
        if (jt + 1 < nkt) LOADKV(jt + 1, buf ^ 1);

        if (k0 > qw + 15) continue;

        uint32_t oKh = OKV + buf * 4 * TB, oKl = oKh + TB, oVh = oKl + TB, oVl = oVh + TB;

        float s[8][4];
#pragma unroll
        for (int i = 0; i < 8; i++)
#pragma unroll
            for (int j = 0; j < 4; j++) s[i][j] = 0.f;

        uint32_t acol = (uint32_t)((lane >> 4) * 8) * 2;
        uint32_t arow = (uint32_t)((16 * w + (lane & 15)) * LQ) * 2;
        uint32_t bro  = (uint32_t)(((lane & 7) + (lane >> 4) * 8) * LQ) * 2;
        uint32_t bco2 = (uint32_t)(((lane >> 3) & 1) * 8) * 2;
#pragma unroll
        for (int ck = 0; ck < 4; ck++) {
            uint32_t kb = (uint32_t)(ck * 16) * 2;
            uint32_t aqh[4], aql[4];
            ldsm4(aqh, sB + arow + acol + kb);
            ldsm4(aql, sB + QB + arow + acol + kb);
#pragma unroll
            for (int pr = 0; pr < 4; pr++) {
                uint32_t ro = (uint32_t)(pr * 16 * LQ) * 2;
                uint32_t bh[4], bl[4];
                ldsm4(bh, sB + oKh + bro + ro + bco2 + kb);
                ldsm4(bl, sB + oKl + bro + ro + bco2 + kb);
#pragma unroll
                for (int hf = 0; hf < 2; hf++) {
                    int tn = pr * 2 + hf;
                    mma16816(s[tn], aqh, bh + hf * 2);
                    mma16816(s[tn], aqh, bl + hf * 2);
                    mma16816(s[tn], aql, bh + hf * 2);
                }
            }
        }

        int a = lane & 3, grp = lane >> 2;
        bool mm = (k0 + 63 > qw);
        float alpha0, alpha1;
#pragma unroll
        for (int half = 0; half < 2; half++) {
            int q = qw + grp + 8 * half;
            const uint4* bp = (const uint4*)(pk + ((size_t)b * Tt + q) * Tt + k0 + 16 * a);
            uint4 u[4] = {bp[0], bp[1], bp[2], bp[3]};
            const uint32_t* ub = (const uint32_t*)u;
            float mx = -1e30f;
#pragma unroll
            for (int nt = 0; nt < 8; nt++)
#pragma unroll
                for (int e = 0; e < 2; e++) {
                    int kk = 2 * nt + e;
                    uint32_t pv = ub[kk];
                    float sv = s[nt][half * 2 + e] + bco * __uint_as_float(pv << 16)
                               + ets[pv >> 16];
                    if (mm && (k0 + 16 * a + kk > q)) sv = -1e30f;
                    s[nt][half * 2 + e] = sv;
                    mx = fmaxf(mx, sv);
                }
            mx = fmaxf(mx, __shfl_xor_sync(0xffffffffu, mx, 1));
            mx = fmaxf(mx, __shfl_xor_sync(0xffffffffu, mx, 2));
            float mold = half ? m1r : m0r;
            float mnew = fmaxf(mold, mx);
            float sum = 0.f;
#pragma unroll
            for (int nt = 0; nt < 8; nt++)
#pragma unroll
                for (int e = 0; e < 2; e++) {
                    float p = __expf(s[nt][half * 2 + e] - mnew);
                    s[nt][half * 2 + e] = p;
                    sum += p;
                }
            sum += __shfl_xor_sync(0xffffffffu, sum, 1);
            sum += __shfl_xor_sync(0xffffffffu, sum, 2);
            float al = __expf(mold - mnew);
            if (half == 0) { m0r = mnew; l0r = l0r * al + sum; alpha0 = al; }
            else           { m1r = mnew; l1r = l1r * al + sum; alpha1 = al; }
        }

#pragma unroll
        for (int nt = 0; nt < 8; nt++) {
            o[nt][0] *= alpha0; o[nt][1] *= alpha0;
            o[nt][2] *= alpha1; o[nt][3] *= alpha1;
        }
#pragma unroll
        for (int j = 0; j < 4; j++) {
            uint32_t ah[4], al2[4];
            pk2(s[2*j][0],   s[2*j][1],   ah[0], al2[0]);
            pk2(s[2*j][2],   s[2*j][3],   ah[1], al2[1]);
            pk2(s[2*j+1][0], s[2*j+1][1], ah[2], al2[2]);
            pk2(s[2*j+1][2], s[2*j+1][3], ah[3], al2[3]);
            uint32_t kb = (uint32_t)(j * 16) * 2;
#pragma unroll
            for (int pr = 0; pr < 4; pr++) {
                uint32_t ro = (uint32_t)(pr * 16 * LQ) * 2;
                uint32_t vh[4], vl[4];
                ldsm4(vh, sB + oVh + bro + ro + bco2 + kb);
                ldsm4(vl, sB + oVl + bro + ro + bco2 + kb);
#pragma unroll
                for (int hf = 0; hf < 2; hf++) {
                    int tn = pr * 2 + hf;
                    mma16816(o[tn], ah, vh + hf * 2);
                    mma16816(o[tn], ah, vl + hf * 2);
                    mma16816(o[tn], al2, vh + hf * 2);
                }
            }
        }
    }

    float il0 = 1.f / l0r, il1 = 1.f / l1r;
    int grp = lane >> 2;
    size_t ix = ((size_t)b * Tt + qw + grp) * Dd + h * 64 + (lane & 3) * 2;
#pragma unroll
    for (int nt = 0; nt < 8; nt++) {
        uint32_t uh, ul;
        pk2(o[nt][0] * il0, o[nt][1] * il0, uh, ul);
        *(uint32_t*)&g_aohi[ix + nt * 8] = uh;
        *(uint32_t*)&g_aolo[ix + nt * 8] = ul;
        pk2(o[nt][2] * il1, o[nt][3] * il1, uh, ul);
        *(uint32_t*)&g_aohi[ix + 8 * Dd + nt * 8] = uh;
        *(uint32_t*)&g_aolo[ix + 8 * Dd + nt * 8] = ul;
    }
}

// ---------------------------------------------------------------------------
extern "C" void kernel_launch(void* const* d_in, const int* in_sizes, int n_in,
                              void* d_out, int out_size) {
    const float* x     = (const float*)d_in[0];
    const float* gadj  = (const float*)d_in[1];
    const int*   etyp  = (const int*)d_in[2];
    const float* wqkv  = (const float*)d_in[3];
    const float* wproj = (const float*)d_in[4];
    const float* abias = (const float*)d_in[5];
    const float* etab  = (const float*)d_in[6];
    float* out = (float*)d_out;

    __nv_bfloat16 *xhi, *xlo, *wqhi, *wqlo, *wphi, *wplo, *aohi, *aolo;
    uint32_t* packp;
    cudaGetSymbolAddress((void**)&xhi,  g_xhi);   cudaGetSymbolAddress((void**)&xlo,  g_xlo);
    cudaGetSymbolAddress((void**)&wqhi, g_wqThi); cudaGetSymbolAddress((void**)&wqlo, g_wqTlo);
    cudaGetSymbolAddress((void**)&wphi, g_wpThi); cudaGetSymbolAddress((void**)&wplo, g_wpTlo);
    cudaGetSymbolAddress((void**)&aohi, g_aohi);  cudaGetSymbolAddress((void**)&aolo, g_aolo);
    cudaGetSymbolAddress((void**)&packp, g_pack);

    const int SHM = 2 * STG_B;                        // 64000
    cudaFuncSetAttribute(mma_gemm, cudaFuncAttributeMaxDynamicSharedMemorySize, SHM);
    const int SMA = OKV + 8 * TB + 128;               // 110720
    cudaFuncSetAttribute(attn_mma, cudaFuncAttributeMaxDynamicSharedMemorySize, SMA);

    split_kernel<<<(Bb * Tt * Dd) / 1024, 256>>>(x, xhi, xlo);
    transsplit<<<dim3(3 * Dd / 32, Dd / 32), dim3(32, 8)>>>(wqkv, wqhi, wqlo, Dd, 3 * Dd);
    transsplit<<<dim3(Dd / 32, Dd / 32), dim3(32, 8)>>>(wproj, wphi, wplo, Dd, Dd);
    pack_bias<<<(int)(((size_t)Bb * Tt * Tt) / 1024), 256>>>(gadj, etyp, packp);

    mma_gemm<<<dim3(3 * Dd / 64, Bb * Tt / 128), 256, SHM>>>(
        xhi, xlo, wqhi, wqlo, 3 * Dd, nullptr, 1);

    attn_mma<<<dim3(Tt / 128, Hh, Bb), 256, SMA>>>(packp, abias, etab);

    mma_gemm<<<dim3(Dd / 64, Bb * Tt / 128), 256, SHM>>>(
        aohi, aolo, wphi, wplo, Dd, out, 0);
}

// round 8
// speedup vs baseline: 1.0441x; 1.0441x over previous
#include <cuda_runtime.h>
#include <cuda_bf16.h>
#include <math.h>
#include <cstdint>

#define Bb 2
#define Tt 2048
#define Dd 1024
#define Hh 16
#define HDd 64
#define NEe 17
#define GK 1024

// ---------------- scratch globals ----------------
__device__ __nv_bfloat16 g_xhi[Bb*Tt*Dd],  g_xlo[Bb*Tt*Dd];
__device__ __nv_bfloat16 g_wqThi[3*Dd*Dd], g_wqTlo[3*Dd*Dd];
__device__ __nv_bfloat16 g_wpThi[Dd*Dd],   g_wpTlo[Dd*Dd];
__device__ __nv_bfloat16 g_qhi[Bb*Hh*Tt*HDd], g_qlo[Bb*Hh*Tt*HDd];   // [b,h,t,d] *0.125
__device__ __nv_bfloat16 g_khi[Bb*Hh*Tt*HDd], g_klo[Bb*Hh*Tt*HDd];   // [b,h,t,d]
__device__ __nv_bfloat16 g_vhi[Bb*Hh*Tt*HDd], g_vlo[Bb*Hh*Tt*HDd];   // [b,h,d,t] key-permuted
__device__ __nv_bfloat16 g_aohi[Bb*Tt*Dd], g_aolo[Bb*Tt*Dd];
__device__ uint32_t g_pack[(size_t)Bb*Tt*Tt];

// ---------------- helpers ----------------
__device__ __forceinline__ uint32_t smem_u32(const void* p) {
    uint32_t a;
    asm("{ .reg .u64 t; cvta.to.shared.u64 t, %1; cvt.u32.u64 %0, t; }" : "=r"(a) : "l"(p));
    return a;
}
__device__ __forceinline__ void ldsm4(uint32_t* r, uint32_t addr) {
    asm volatile("ldmatrix.sync.aligned.m8n8.x4.shared.b16 {%0,%1,%2,%3}, [%4];"
        : "=r"(r[0]), "=r"(r[1]), "=r"(r[2]), "=r"(r[3]) : "r"(addr));
}
__device__ __forceinline__ void mma16816(float* c, const uint32_t* a, const uint32_t* b) {
    asm volatile("mma.sync.aligned.m16n8k16.row.col.f32.bf16.bf16.f32 "
        "{%0,%1,%2,%3}, {%4,%5,%6,%7}, {%8,%9}, {%0,%1,%2,%3};"
        : "+f"(c[0]), "+f"(c[1]), "+f"(c[2]), "+f"(c[3])
        : "r"(a[0]), "r"(a[1]), "r"(a[2]), "r"(a[3]), "r"(b[0]), "r"(b[1]));
}
__device__ __forceinline__ void pk2(float a, float b, uint32_t& hi, uint32_t& lo) {
    __nv_bfloat16 ha = __float2bfloat16(a), hb = __float2bfloat16(b);
    __nv_bfloat162 hh(ha, hb); hi = *(uint32_t*)&hh;
    __nv_bfloat162 ll(__float2bfloat16(a - __bfloat162float(ha)),
                      __float2bfloat16(b - __bfloat162float(hb)));
    lo = *(uint32_t*)&ll;
}
__device__ __forceinline__ void cpa16(uint32_t s, const void* g) {
    asm volatile("cp.async.cg.shared.global [%0], [%1], 16;" :: "r"(s), "l"(g));
}
#define CPC()  asm volatile("cp.async.commit_group;" ::: "memory")
#define CPW0() asm volatile("cp.async.wait_group 0;" ::: "memory")

// ---------------- prep kernels ----------------
__global__ __launch_bounds__(256) void split_kernel(const float* __restrict__ s,
                                                    __nv_bfloat16* __restrict__ hi,
                                                    __nv_bfloat16* __restrict__ lo) {
    int i = (blockIdx.x * 256 + threadIdx.x) * 4;
    float4 v = *(const float4*)(s + i);
    float f[4] = {v.x, v.y, v.z, v.w};
    __nv_bfloat16 h[4], l[4];
#pragma unroll
    for (int j = 0; j < 4; j++) {
        h[j] = __float2bfloat16(f[j]);
        l[j] = __float2bfloat16(f[j] - __bfloat162float(h[j]));
    }
    *(__nv_bfloat162*)&hi[i]     = __nv_bfloat162(h[0], h[1]);
    *(__nv_bfloat162*)&hi[i + 2] = __nv_bfloat162(h[2], h[3]);
    *(__nv_bfloat162*)&lo[i]     = __nv_bfloat162(l[0], l[1]);
    *(__nv_bfloat162*)&lo[i + 2] = __nv_bfloat162(l[2], l[3]);
}

__global__ __launch_bounds__(256) void transsplit(const float* __restrict__ W,
                                                  __nv_bfloat16* __restrict__ thi,
                                                  __nv_bfloat16* __restrict__ tlo,
                                                  int Kdim, int Ndim) {
    __shared__ float t[32][33];
    int n0 = blockIdx.x * 32, k0 = blockIdx.y * 32;
    int tx = threadIdx.x, ty = threadIdx.y;
#pragma unroll
    for (int j = 0; j < 32; j += 8)
        t[ty + j][tx] = W[(size_t)(k0 + ty + j) * Ndim + n0 + tx];
    __syncthreads();
#pragma unroll
    for (int j = 0; j < 32; j += 8) {
        float v = t[tx][ty + j];
        __nv_bfloat16 h = __float2bfloat16(v);
        size_t o = (size_t)(n0 + ty + j) * Kdim + k0 + tx;
        thi[o] = h;
        tlo[o] = __float2bfloat16(v - __bfloat162float(h));
    }
}

__global__ __launch_bounds__(256) void pack_bias(const float* __restrict__ adj,
                                                 const int* __restrict__ ety,
                                                 uint32_t* __restrict__ out) {
    size_t i = ((size_t)blockIdx.x * 256 + threadIdx.x) * 4;
    float4 a = *(const float4*)(adj + i);
    int4 t = *(const int4*)(ety + i);
    uint4 r;
    r.x = ((uint32_t)t.x << 16) | (uint32_t)__bfloat16_as_ushort(__float2bfloat16(a.x));
    r.y = ((uint32_t)t.y << 16) | (uint32_t)__bfloat16_as_ushort(__float2bfloat16(a.y));
    r.z = ((uint32_t)t.z << 16) | (uint32_t)__bfloat16_as_ushort(__float2bfloat16(a.z));
    r.w = ((uint32_t)t.w << 16) | (uint32_t)__bfloat16_as_ushort(__float2bfloat16(a.w));
    *(uint4*)(out + i) = r;
}

// ---------------------------------------------------------------------------
// HMMA GEMM (R5 version): 128x128 tile, LDG prefetch double-buffer.
// mode 0: fp32 Cout. mode 1: QKV epilogue -> bf16 hi/lo, Q *0.125,
//   V -> [b,h,d,t] with key-permutation baked in.
// ---------------------------------------------------------------------------
#define KC 32
#define LDP 40
#define TILE_B (128 * LDP * 2)
#define BUF_B  (4 * TILE_B)

__global__ __launch_bounds__(256)
void mma_gemm(const __nv_bfloat16* __restrict__ Ahi, const __nv_bfloat16* __restrict__ Alo,
              const __nv_bfloat16* __restrict__ Bhi, const __nv_bfloat16* __restrict__ Blo,
              int Ncols, float* __restrict__ Cout, int mode) {
    extern __shared__ char smem[];
    uint32_t sb = smem_u32(smem);
    int tid = threadIdx.x, wid = tid >> 5, lane = tid & 31;
    int wm = wid & 3, wn = wid >> 2;
    int m0 = blockIdx.y * 128, n0 = blockIdx.x * 128;

    int r_ld  = tid >> 2;
    int c8_ld = (tid & 3) * 8;
    const __nv_bfloat16* srcs[4] = {
        Ahi + (size_t)m0 * GK, Alo + (size_t)m0 * GK,
        Bhi + (size_t)n0 * GK, Blo + (size_t)n0 * GK };

    uint32_t a_off = (uint32_t)((wm * 32 + (lane & 15)) * LDP + (lane >> 4) * 8) * 2;
    uint32_t b_off = (uint32_t)((wn * 64 + (lane & 7) + (lane >> 4) * 8) * LDP
                                + ((lane >> 3) & 1) * 8) * 2;

    float acc[2][8][4];
#pragma unroll
    for (int i = 0; i < 2; i++)
#pragma unroll
        for (int j = 0; j < 8; j++)
#pragma unroll
            for (int k = 0; k < 4; k++) acc[i][j][k] = 0.f;

    uint4 pf[4][2];
#pragma unroll
    for (int t = 0; t < 4; t++)
#pragma unroll
        for (int i = 0; i < 2; i++)
            pf[t][i] = *(const uint4*)(srcs[t] + (size_t)(r_ld + i * 64) * GK + c8_ld);
    {
        char* base = smem;
#pragma unroll
        for (int t = 0; t < 4; t++)
#pragma unroll
            for (int i = 0; i < 2; i++)
                *(uint4*)(base + t * TILE_B + ((r_ld + i * 64) * LDP + c8_ld) * 2) = pf[t][i];
    }
    __syncthreads();

    const int NCH = GK / KC;
    for (int kc = 0; kc < NCH; kc++) {
        int buf = kc & 1;
        if (kc + 1 < NCH) {
            size_t go = (size_t)(kc + 1) * KC;
#pragma unroll
            for (int t = 0; t < 4; t++)
#pragma unroll
                for (int i = 0; i < 2; i++)
                    pf[t][i] = *(const uint4*)(srcs[t] + (size_t)(r_ld + i * 64) * GK + go + c8_ld);
        }
        uint32_t sAh = sb + buf * BUF_B + a_off;
        uint32_t sAl = sAh + TILE_B;
        uint32_t sBh = sb + buf * BUF_B + 2 * TILE_B + b_off;
        uint32_t sBl = sBh + TILE_B;
#pragma unroll
        for (int ks = 0; ks < 2; ks++) {
            uint32_t kb = (uint32_t)(ks * 16) * 2;
            uint32_t ah[2][4], al[2][4];
#pragma unroll
            for (int tm = 0; tm < 2; tm++) {
                uint32_t ro = (uint32_t)(tm * 16 * LDP) * 2;
                ldsm4(ah[tm], sAh + ro + kb);
                ldsm4(al[tm], sAl + ro + kb);
            }
#pragma unroll
            for (int pr = 0; pr < 4; pr++) {
                uint32_t po = (uint32_t)(pr * 16 * LDP) * 2;
                uint32_t bh[4], bl[4];
                ldsm4(bh, sBh + po + kb);
                ldsm4(bl, sBl + po + kb);
#pragma unroll
                for (int hf = 0; hf < 2; hf++) {
                    int tn = pr * 2 + hf;
#pragma unroll
                    for (int tm = 0; tm < 2; tm++) {
                        mma16816(acc[tm][tn], ah[tm], bh + hf * 2);
                        mma16816(acc[tm][tn], ah[tm], bl + hf * 2);
                        mma16816(acc[tm][tn], al[tm], bh + hf * 2);
                    }
                }
            }
        }
        if (kc + 1 < NCH) {
            char* base = smem + (1 - buf) * BUF_B;
#pragma unroll
            for (int t = 0; t < 4; t++)
#pragma unroll
                for (int i = 0; i < 2; i++)
                    *(uint4*)(base + t * TILE_B + ((r_ld + i * 64) * LDP + c8_ld) * 2) = pf[t][i];
            __syncthreads();
        }
    }

    int rbase = m0 + wm * 32 + (lane >> 2);
    int cbase = n0 + wn * 64 + (lane & 3) * 2;

    if (mode == 0) {
#pragma unroll
        for (int tm = 0; tm < 2; tm++)
#pragma unroll
            for (int tn = 0; tn < 8; tn++)
#pragma unroll
                for (int half = 0; half < 2; half++) {
                    int m = rbase + tm * 16 + half * 8;
                    *(float2*)&Cout[(size_t)m * Ncols + cbase + tn * 8] =
                        make_float2(acc[tm][tn][half * 2], acc[tm][tn][half * 2 + 1]);
                }
        return;
    }

    int which = n0 >> 10;
    if (which < 2) {
        float sc = (which == 0) ? 0.125f : 1.0f;
        __nv_bfloat16* dh = which ? g_khi : g_qhi;
        __nv_bfloat16* dl = which ? g_klo : g_qlo;
#pragma unroll
        for (int tm = 0; tm < 2; tm++)
#pragma unroll
            for (int tn = 0; tn < 8; tn++)
#pragma unroll
                for (int half = 0; half < 2; half++) {
                    int m = rbase + tm * 16 + half * 8;
                    int n = cbase + tn * 8;
                    int h = (n & 1023) >> 6, d = n & 63;
                    int bI = m >> 11, t = m & 2047;
                    size_t ix = ((size_t)(bI * Hh + h) * Tt + t) * HDd + d;
                    uint32_t uh, ul;
                    pk2(acc[tm][tn][half * 2] * sc, acc[tm][tn][half * 2 + 1] * sc, uh, ul);
                    *(uint32_t*)&dh[ix] = uh;
                    *(uint32_t*)&dl[ix] = ul;
                }
    } else {
        // V: transpose via smem, store [b,h,d,t] with key-permutation baked in
        float* buf = (float*)smem;
        __syncthreads();
#pragma unroll
        for (int tm = 0; tm < 2; tm++)
#pragma unroll
            for (int tn = 0; tn < 8; tn++)
#pragma unroll
                for (int half = 0; half < 2; half++) {
                    int nl = wn * 64 + tn * 8 + (lane & 3) * 2;
                    int ml = wm * 32 + (lane >> 2) + tm * 16 + half * 8;
                    buf[nl * 132 + ml]       = acc[tm][tn][half * 2];
                    buf[(nl + 1) * 132 + ml] = acc[tm][tn][half * 2 + 1];
                }
        __syncthreads();
        int nl = tid >> 1, mh = (tid & 1) * 64;
        int n = n0 + nl;
        int h = (n & 1023) >> 6, d = n & 63;
        int bI = m0 >> 11, t0 = (m0 & 2047) + mh;
        size_t base = ((size_t)(bI * Hh + h) * HDd + d) * Tt + t0;
#pragma unroll
        for (int g = 0; g < 8; g++) {
            __nv_bfloat16 hi8[8], lo8[8];
#pragma unroll
            for (int e = 0; e < 8; e++) {
                int c = g * 8 + e;
                int src = 16 * ((c >> 1) & 3) + 2 * (c >> 3) + (c & 1);
                float f = buf[nl * 132 + mh + src];
                hi8[e] = __float2bfloat16(f);
                lo8[e] = __float2bfloat16(f - __bfloat162float(hi8[e]));
            }
            *(uint4*)&g_vhi[base + g * 8] = *(uint4*)hi8;
            *(uint4*)&g_vlo[base + g * 8] = *(uint4*)lo8;
        }
    }
}

// ---------------------------------------------------------------------------
// HMMA flash attention: q-tile 128, k-tile 64, cp.async double-buffered KV,
// LPT ordering (longest q-tiles first).
// ---------------------------------------------------------------------------
#define LQ 72
#define QB (128 * LQ * 2)
#define TB (64 * LQ * 2)
#define OKV (2 * QB)

__global__ __launch_bounds__(256, 2) void attn_mma(
    const uint32_t* __restrict__ pk, const float* __restrict__ adj_bias,
    const float* __restrict__ edge_table) {
    extern __shared__ char sm[];
    uint32_t sB = smem_u32(sm);
    float* ets = (float*)(sm + OKV + 8 * TB);

    int tid = threadIdx.x, w = tid >> 5, lane = tid & 31;
    int qt = (int)(gridDim.x - 1 - blockIdx.x);      // LPT: big tiles first
    int h = blockIdx.y, b = blockIdx.z;
    int q0 = qt * 128, qw = q0 + 16 * w;
    float bco = adj_bias[h];
    if (tid < NEe) ets[tid] = edge_table[tid * Hh + h];

    {   // Q tile (pre-scaled bf16 hi/lo)
        const __nv_bfloat16* qh = g_qhi + ((size_t)(b * Hh + h) * Tt + q0) * HDd;
        const __nv_bfloat16* ql = g_qlo + ((size_t)(b * Hh + h) * Tt + q0) * HDd;
        __nv_bfloat16* sQh = (__nv_bfloat16*)sm;
        __nv_bfloat16* sQl = sQh + 128 * LQ;
        int r = tid >> 1, cg = (tid & 1) * 32;
#pragma unroll
        for (int u = 0; u < 4; u++) {
            *(uint4*)&sQh[r * LQ + cg + u * 8] = *(const uint4*)&qh[(size_t)r * 64 + cg + u * 8];
            *(uint4*)&sQl[r * LQ + cg + u * 8] = *(const uint4*)&ql[(size_t)r * 64 + cg + u * 8];
        }
    }

    int c = tid >> 2, dg = (tid & 3) * 16;
    int gkp = 16 * ((c >> 1) & 3) + 2 * (c >> 3) + (c & 1);
    uint32_t krow = (uint32_t)(c * LQ + dg) * 2;
    const __nv_bfloat16* bkh = g_khi + ((size_t)(b * Hh + h) * Tt + gkp) * HDd + dg;
    const __nv_bfloat16* bkl = g_klo + ((size_t)(b * Hh + h) * Tt + gkp) * HDd + dg;
    const __nv_bfloat16* bvh = g_vhi + ((size_t)(b * Hh + h) * HDd + c) * Tt + dg;
    const __nv_bfloat16* bvl = g_vlo + ((size_t)(b * Hh + h) * HDd + c) * Tt + dg;

#define LOADKV(jt, bf) do {                                                     \
    int _k0 = (jt) * 64;                                                        \
    uint32_t _bs = sB + OKV + (bf) * 4 * TB;                                    \
    cpa16(_bs + krow,               bkh + (size_t)_k0 * HDd);                   \
    cpa16(_bs + krow + 16,          bkh + (size_t)_k0 * HDd + 8);               \
    cpa16(_bs + TB + krow,          bkl + (size_t)_k0 * HDd);                   \
    cpa16(_bs + TB + krow + 16,     bkl + (size_t)_k0 * HDd + 8);               \
    cpa16(_bs + 2 * TB + krow,      bvh + _k0);                                 \
    cpa16(_bs + 2 * TB + krow + 16, bvh + _k0 + 8);                             \
    cpa16(_bs + 3 * TB + krow,      bvl + _k0);                                 \
    cpa16(_bs + 3 * TB + krow + 16, bvl + _k0 + 8);                             \
    CPC();                                                                      \
} while (0)

    float o[8][4];
#pragma unroll
    for (int i = 0; i < 8; i++)
#pragma unroll
        for (int j = 0; j < 4; j++) o[i][j] = 0.f;
    float m0r = -1e30f, m1r = -1e30f, l0r = 0.f, l1r = 0.f;

    LOADKV(0, 0);

    int nkt = 2 * qt + 2;
    for (int jt = 0; jt < nkt; jt++) {
        int k0 = jt * 64;
        int buf = jt & 1;
        CPW0();
        __syncthreads();
        if (jt + 1 < nkt) LOADKV(jt + 1, buf ^ 1);

        if (k0 > qw + 15) continue;

        uint32_t oKh = OKV + buf * 4 * TB, oKl = oKh + TB, oVh = oKl + TB, oVl = oVh + TB;

        float s[8][4];
#pragma unroll
        for (int i = 0; i < 8; i++)
#pragma unroll
            for (int j = 0; j < 4; j++) s[i][j] = 0.f;

        uint32_t acol = (uint32_t)((lane >> 4) * 8) * 2;
        uint32_t arow = (uint32_t)((16 * w + (lane & 15)) * LQ) * 2;
        uint32_t bro  = (uint32_t)(((lane & 7) + (lane >> 4) * 8) * LQ) * 2;
        uint32_t bco2 = (uint32_t)(((lane >> 3) & 1) * 8) * 2;
#pragma unroll
        for (int ck = 0; ck < 4; ck++) {
            uint32_t kb = (uint32_t)(ck * 16) * 2;
            uint32_t aqh[4], aql[4];
            ldsm4(aqh, sB + arow + acol + kb);
            ldsm4(aql, sB + QB + arow + acol + kb);
#pragma unroll
            for (int pr = 0; pr < 4; pr++) {
                uint32_t ro = (uint32_t)(pr * 16 * LQ) * 2;
                uint32_t bh[4], bl[4];
                ldsm4(bh, sB + oKh + bro + ro + bco2 + kb);
                ldsm4(bl, sB + oKl + bro + ro + bco2 + kb);
#pragma unroll
                for (int hf = 0; hf < 2; hf++) {
                    int tn = pr * 2 + hf;
                    mma16816(s[tn], aqh, bh + hf * 2);
                    mma16816(s[tn], aqh, bl + hf * 2);
                    mma16816(s[tn], aql, bh + hf * 2);
                }
            }
        }

        int a = lane & 3, grp = lane >> 2;
        bool mm = (k0 + 63 > qw);
        float alpha0, alpha1;
#pragma unroll
        for (int half = 0; half < 2; half++) {
            int q = qw + grp + 8 * half;
            const uint4* bp = (const uint4*)(pk + ((size_t)b * Tt + q) * Tt + k0 + 16 * a);
            uint4 u[4] = {bp[0], bp[1], bp[2], bp[3]};
            const uint32_t* ub = (const uint32_t*)u;
            float mx = -1e30f;
#pragma unroll
            for (int nt = 0; nt < 8; nt++)
#pragma unroll
                for (int e = 0; e < 2; e++) {
                    int kk = 2 * nt + e;
                    uint32_t pv = ub[kk];
                    float sv = s[nt][half * 2 + e] + bco * __uint_as_float(pv << 16)
                               + ets[pv >> 16];
                    if (mm && (k0 + 16 * a + kk > q)) sv = -1e30f;
                    s[nt][half * 2 + e] = sv;
                    mx = fmaxf(mx, sv);
                }
            mx = fmaxf(mx, __shfl_xor_sync(0xffffffffu, mx, 1));
            mx = fmaxf(mx, __shfl_xor_sync(0xffffffffu, mx, 2));
            float mold = half ? m1r : m0r;
            float mnew = fmaxf(mold, mx);
            float sum = 0.f;
#pragma unroll
            for (int nt = 0; nt < 8; nt++)
#pragma unroll
                for (int e = 0; e < 2; e++) {
                    float p = __expf(s[nt][half * 2 + e] - mnew);
                    s[nt][half * 2 + e] = p;
                    sum += p;
                }
            sum += __shfl_xor_sync(0xffffffffu, sum, 1);
            sum += __shfl_xor_sync(0xffffffffu, sum, 2);
            float al = __expf(mold - mnew);
            if (half == 0) { m0r = mnew; l0r = l0r * al + sum; alpha0 = al; }
            else           { m1r = mnew; l1r = l1r * al + sum; alpha1 = al; }
        }

#pragma unroll
        for (int nt = 0; nt < 8; nt++) {
            o[nt][0] *= alpha0; o[nt][1] *= alpha0;
            o[nt][2] *= alpha1; o[nt][3] *= alpha1;
        }
#pragma unroll
        for (int j = 0; j < 4; j++) {
            uint32_t ah[4], al2[4];
            pk2(s[2*j][0],   s[2*j][1],   ah[0], al2[0]);
            pk2(s[2*j][2],   s[2*j][3],   ah[1], al2[1]);
            pk2(s[2*j+1][0], s[2*j+1][1], ah[2], al2[2]);
            pk2(s[2*j+1][2], s[2*j+1][3], ah[3], al2[3]);
            uint32_t kb = (uint32_t)(j * 16) * 2;
#pragma unroll
            for (int pr = 0; pr < 4; pr++) {
                uint32_t ro = (uint32_t)(pr * 16 * LQ) * 2;
                uint32_t vh[4], vl[4];
                ldsm4(vh, sB + oVh + bro + ro + bco2 + kb);
                ldsm4(vl, sB + oVl + bro + ro + bco2 + kb);
#pragma unroll
                for (int hf = 0; hf < 2; hf++) {
                    int tn = pr * 2 + hf;
                    mma16816(o[tn], ah, vh + hf * 2);
                    mma16816(o[tn], ah, vl + hf * 2);
                    mma16816(o[tn], al2, vh + hf * 2);
                }
            }
        }
    }

    float il0 = 1.f / l0r, il1 = 1.f / l1r;
    int grp = lane >> 2;
    size_t ix = ((size_t)b * Tt + qw + grp) * Dd + h * 64 + (lane & 3) * 2;
#pragma unroll
    for (int nt = 0; nt < 8; nt++) {
        uint32_t uh, ul;
        pk2(o[nt][0] * il0, o[nt][1] * il0, uh, ul);
        *(uint32_t*)&g_aohi[ix + nt * 8] = uh;
        *(uint32_t*)&g_aolo[ix + nt * 8] = ul;
        pk2(o[nt][2] * il1, o[nt][3] * il1, uh, ul);
        *(uint32_t*)&g_aohi[ix + 8 * Dd + nt * 8] = uh;
        *(uint32_t*)&g_aolo[ix + 8 * Dd + nt * 8] = ul;
    }
}

// ---------------------------------------------------------------------------
extern "C" void kernel_launch(void* const* d_in, const int* in_sizes, int n_in,
                              void* d_out, int out_size) {
    const float* x     = (const float*)d_in[0];
    const float* gadj  = (const float*)d_in[1];
    const int*   etyp  = (const int*)d_in[2];
    const float* wqkv  = (const float*)d_in[3];
    const float* wproj = (const float*)d_in[4];
    const float* abias = (const float*)d_in[5];
    const float* etab  = (const float*)d_in[6];
    float* out = (float*)d_out;

    __nv_bfloat16 *xhi, *xlo, *wqhi, *wqlo, *wphi, *wplo, *aohi, *aolo;
    uint32_t* packp;
    cudaGetSymbolAddress((void**)&xhi,  g_xhi);   cudaGetSymbolAddress((void**)&xlo,  g_xlo);
    cudaGetSymbolAddress((void**)&wqhi, g_wqThi); cudaGetSymbolAddress((void**)&wqlo, g_wqTlo);
    cudaGetSymbolAddress((void**)&wphi, g_wpThi); cudaGetSymbolAddress((void**)&wplo, g_wpTlo);
    cudaGetSymbolAddress((void**)&aohi, g_aohi);  cudaGetSymbolAddress((void**)&aolo, g_aolo);
    cudaGetSymbolAddress((void**)&packp, g_pack);

    const int SHM = 2 * BUF_B;                        // 81920
    cudaFuncSetAttribute(mma_gemm, cudaFuncAttributeMaxDynamicSharedMemorySize, SHM);
    const int SMA = OKV + 8 * TB + 128;               // 110720
    cudaFuncSetAttribute(attn_mma, cudaFuncAttributeMaxDynamicSharedMemorySize, SMA);

    split_kernel<<<(Bb * Tt * Dd) / 1024, 256>>>(x, xhi, xlo);
    transsplit<<<dim3(3 * Dd / 32, Dd / 32), dim3(32, 8)>>>(wqkv, wqhi, wqlo, Dd, 3 * Dd);
    transsplit<<<dim3(Dd / 32, Dd / 32), dim3(32, 8)>>>(wproj, wphi, wplo, Dd, Dd);
    pack_bias<<<(int)(((size_t)Bb * Tt * Tt) / 1024), 256>>>(gadj, etyp, packp);

    mma_gemm<<<dim3(3 * Dd / 128, Bb * Tt / 128), 256, SHM>>>(
        xhi, xlo, wqhi, wqlo, 3 * Dd, nullptr, 1);

    attn_mma<<<dim3(Tt / 128, Hh, Bb), 256, SMA>>>(packp, abias, etab);

    mma_gemm<<<dim3(Dd / 128, Bb * Tt / 128), 256, SHM>>>(
        aohi, aolo, wphi, wplo, Dd, out, 0);
}